// round 1
// baseline (speedup 1.0000x reference)
#include <cuda_runtime.h>

#define NN 50000
#define EE 800000
#define ET (EE + NN)
#define FD 128      // H*HID
#define EDD 16      // edge_dim
#define HIDD 32
#define HH 4
#define OUTD 64
#define NEGS 0.1f

// ---------------- scratch (device globals; no runtime allocation) ------------
__device__ float g_f0[NN * HIDD];          // embed out / layer1 out
__device__ float g_f1[NN * HIDD];          // layer0 out
__device__ float g_xl[(size_t)NN * FD];
__device__ float g_xr[(size_t)NN * FD];
__device__ float g_loop[NN * EDD];
__device__ float g_cnt[NN];
__device__ float g_alpha[(size_t)ET * HH];
__device__ float g_amax[NN * HH];
__device__ float g_den[NN * HH];

__device__ __forceinline__ float lrelu(float v) { return v > 0.f ? v : NEGS * v; }

__device__ __forceinline__ void atomicMaxF(float* addr, float v) {
    if (v >= 0.f) atomicMax((int*)addr, __float_as_int(v));
    else          atomicMin((unsigned int*)addr, __float_as_uint(v));
}

// ---------------- input embed: Linear(128->32) + BN(eval) + LeakyReLU --------
__global__ void k_embed(const float* __restrict__ x, const float* __restrict__ W0,
                        const float* __restrict__ b0, const float* __restrict__ bng,
                        const float* __restrict__ bnb, const float* __restrict__ bnm,
                        const float* __restrict__ bnv) {
    __shared__ float W0t[128 * 32];   // transposed: [k][j]
    int tid = threadIdx.x;
    for (int i = tid; i < 128 * 32; i += blockDim.x) {
        int k = i >> 5, j = i & 31;
        W0t[i] = W0[j * 128 + k];
    }
    __syncthreads();
    int warp = tid >> 5, lane = tid & 31;
    int n = blockIdx.x * 8 + warp;
    if (n >= NN) return;
    const float* xr_ = x + (size_t)n * 128;
    float acc = 0.f;
#pragma unroll 8
    for (int k = 0; k < 128; k++) acc += xr_[k] * W0t[k * 32 + lane];
    acc += b0[lane];
    float sc = bng[lane] * rsqrtf(bnv[lane] + 1e-5f);
    acc = (acc - bnm[lane]) * sc + bnb[lane];
    g_f0[n * 32 + lane] = lrelu(acc);
}

// ---------------- self-loop attr: per-dst mean of edge_attr ------------------
__global__ void k_zero_loop() {
    int i = blockIdx.x * blockDim.x + threadIdx.x;
    if (i < NN) g_cnt[i] = 0.f;
    if (i < NN * EDD) g_loop[i] = 0.f;
}
__global__ void k_loop_accum(const int* __restrict__ ei, const float* __restrict__ ea) {
    int i = blockIdx.x * blockDim.x + threadIdx.x;
    if (i >= EE * EDD) return;
    int e = i >> 4, d = i & 15;
    int dst = ei[EE + e];
    atomicAdd(&g_loop[dst * EDD + d], ea[i]);
    if (d == 0) atomicAdd(&g_cnt[dst], 1.f);
}
__global__ void k_loop_div() {
    int i = blockIdx.x * blockDim.x + threadIdx.x;
    if (i >= NN * EDD) return;
    int n = i >> 4;
    g_loop[i] /= fmaxf(g_cnt[n], 1.f);
}

// ---------------- node transforms: xl = f@Wl^T+bl, xr = f@Wr^T+br ------------
__global__ void k_xlxr(const float* __restrict__ feat,
                       const float* __restrict__ Wl, const float* __restrict__ bl,
                       const float* __restrict__ Wr, const float* __restrict__ br) {
    __shared__ float WlT[32 * 128];
    __shared__ float WrT[32 * 128];
    int tid = threadIdx.x;
    for (int i = tid; i < 32 * 128; i += blockDim.x) {
        int k = i >> 7, j = i & 127;
        WlT[i] = Wl[j * 32 + k];
        WrT[i] = Wr[j * 32 + k];
    }
    __syncthreads();
    int j = tid & 127;
    int n = blockIdx.x * 2 + (tid >> 7);
    if (n >= NN) return;
    const float* fr = feat + n * 32;
    float al = 0.f, ar = 0.f;
#pragma unroll
    for (int k = 0; k < 32; k++) {
        float fv = fr[k];
        al += fv * WlT[k * 128 + j];
        ar += fv * WrT[k * 128 + j];
    }
    g_xl[(size_t)n * 128 + j] = al + bl[j];
    g_xr[(size_t)n * 128 + j] = ar + br[j];
}

// ---------------- per-layer state init ---------------------------------------
__global__ void k_init(float* __restrict__ outbuf, const float* __restrict__ bias) {
    int i = blockIdx.x * blockDim.x + threadIdx.x;
    if (i < NN * HH) { g_amax[i] = __int_as_float(0xff800000); g_den[i] = 0.f; }
    if (i < NN * HIDD) outbuf[i] = bias[i & 31];
}

// ---------------- pass A: alpha per (edge,head) + segment max ----------------
__global__ void k_alpha(const int* __restrict__ ei, const float* __restrict__ eattr,
                        const float* __restrict__ We, const float* __restrict__ att) {
    __shared__ float WeT[16 * 128];   // [d][j]
    __shared__ float attS[128];
    int tid = threadIdx.x;
    for (int i = tid; i < 16 * 128; i += blockDim.x) {
        int d = i >> 7, j = i & 127;
        WeT[i] = We[j * 16 + d];
    }
    if (tid < 128) attS[tid] = att[tid];
    __syncthreads();
    int lane = tid & 31;
    int e = blockIdx.x * 8 + (tid >> 5);
    if (e >= ET) return;
    int src, dst;
    float eav = 0.f;
    if (e < EE) {
        src = ei[e]; dst = ei[EE + e];
        if (lane < 16) eav = eattr[(size_t)e * 16 + lane];
    } else {
        src = dst = e - EE;
        if (lane < 16) eav = g_loop[(e - EE) * 16 + lane];
    }
    const float* xls = g_xl + (size_t)src * 128;
    const float* xrd = g_xr + (size_t)dst * 128;
    float a[4];
#pragma unroll
    for (int h = 0; h < 4; h++) {
        float eaj = 0.f;
#pragma unroll
        for (int d = 0; d < 16; d++)
            eaj += __shfl_sync(0xffffffffu, eav, d) * WeT[d * 128 + h * 32 + lane];
        float m = lrelu(xls[h * 32 + lane] + xrd[h * 32 + lane] + eaj);
        float v = m * attS[h * 32 + lane];
#pragma unroll
        for (int off = 16; off; off >>= 1) v += __shfl_down_sync(0xffffffffu, v, off);
        a[h] = v;
    }
    if (lane == 0) {
        size_t base = (size_t)e * 4;
        g_alpha[base + 0] = a[0]; g_alpha[base + 1] = a[1];
        g_alpha[base + 2] = a[2]; g_alpha[base + 3] = a[3];
        atomicMaxF(&g_amax[dst * 4 + 0], a[0]);
        atomicMaxF(&g_amax[dst * 4 + 1], a[1]);
        atomicMaxF(&g_amax[dst * 4 + 2], a[2]);
        atomicMaxF(&g_amax[dst * 4 + 3], a[3]);
    }
}

// ---------------- pass B: exp + segment sum (denominator) --------------------
__global__ void k_softmax_den(const int* __restrict__ ei) {
    long long i = (long long)blockIdx.x * blockDim.x + threadIdx.x;
    if (i >= (long long)ET * HH) return;
    int e = (int)(i >> 2), h = (int)(i & 3);
    int dst = (e < EE) ? ei[EE + e] : (e - EE);
    float ex = __expf(g_alpha[i] - g_amax[dst * 4 + h]);
    g_alpha[i] = ex;
    atomicAdd(&g_den[dst * 4 + h], ex);
}

// ---------------- pass C: weighted aggregate (mean over heads folded in) -----
__global__ void k_aggregate(const int* __restrict__ ei, float* __restrict__ outbuf) {
    int tid = threadIdx.x;
    int lane = tid & 31;
    int e = blockIdx.x * 8 + (tid >> 5);
    if (e >= ET) return;
    int src, dst;
    if (e < EE) { src = ei[e]; dst = ei[EE + e]; }
    else        { src = dst = e - EE; }
    float w = 0.f;
    if (lane < 4) w = g_alpha[(size_t)e * 4 + lane] / g_den[dst * 4 + lane];
    float w0 = __shfl_sync(0xffffffffu, w, 0);
    float w1 = __shfl_sync(0xffffffffu, w, 1);
    float w2 = __shfl_sync(0xffffffffu, w, 2);
    float w3 = __shfl_sync(0xffffffffu, w, 3);
    const float* xls = g_xl + (size_t)src * 128;
    float acc = 0.25f * (w0 * xls[lane] + w1 * xls[32 + lane] +
                         w2 * xls[64 + lane] + w3 * xls[96 + lane]);
    atomicAdd(&outbuf[dst * 32 + lane], acc);
}

// ---------------- output head: Linear(32->64) + LeakyReLU --------------------
__global__ void k_final(const float* __restrict__ feat, const float* __restrict__ Wout,
                        const float* __restrict__ bout, float* __restrict__ y) {
    __shared__ float WT[32 * 64];   // [c][o]
    int tid = threadIdx.x;
    for (int i = tid; i < 32 * 64; i += blockDim.x) {
        int c = i >> 6, o = i & 63;
        WT[i] = Wout[o * 32 + c];
    }
    __syncthreads();
    int o = tid & 63;
    int n = blockIdx.x * 4 + (tid >> 6);
    if (n >= NN) return;
    const float* fr = feat + n * 32;
    float acc = 0.f;
#pragma unroll
    for (int c = 0; c < 32; c++) acc += fr[c] * WT[c * 64 + o];
    acc += bout[o];
    y[(size_t)n * 64 + o] = lrelu(acc);
}

// =============================================================================
extern "C" void kernel_launch(void* const* d_in, const int* in_sizes, int n_in,
                              void* d_out, int out_size) {
    const float* x     = (const float*)d_in[0];
    const int*   ei    = (const int*)d_in[1];
    const float* eattr = (const float*)d_in[2];
    const float* W0    = (const float*)d_in[3];
    const float* b0    = (const float*)d_in[4];
    const float* bng   = (const float*)d_in[5];
    const float* bnb   = (const float*)d_in[6];
    const float* bnm   = (const float*)d_in[7];
    const float* bnv   = (const float*)d_in[8];
    const float* Wl[2]   = {(const float*)d_in[9],  (const float*)d_in[16]};
    const float* bl[2]   = {(const float*)d_in[10], (const float*)d_in[17]};
    const float* Wr[2]   = {(const float*)d_in[11], (const float*)d_in[18]};
    const float* br[2]   = {(const float*)d_in[12], (const float*)d_in[19]};
    const float* We[2]   = {(const float*)d_in[13], (const float*)d_in[20]};
    const float* att[2]  = {(const float*)d_in[14], (const float*)d_in[21]};
    const float* bias[2] = {(const float*)d_in[15], (const float*)d_in[22]};
    const float* Wout  = (const float*)d_in[23];
    const float* bout  = (const float*)d_in[24];
    float* y = (float*)d_out;

    float *f0, *f1;
    cudaGetSymbolAddress((void**)&f0, g_f0);
    cudaGetSymbolAddress((void**)&f1, g_f1);

    k_embed<<<(NN + 7) / 8, 256>>>(x, W0, b0, bng, bnb, bnm, bnv);
    k_zero_loop<<<(NN * EDD + 255) / 256, 256>>>();
    k_loop_accum<<<(EE * EDD + 255) / 256, 256>>>(ei, eattr);
    k_loop_div<<<(NN * EDD + 255) / 256, 256>>>();

    float* fin = f0;
    float* fout = f1;
    for (int l = 0; l < 2; l++) {
        k_xlxr<<<NN / 2, 256>>>(fin, Wl[l], bl[l], Wr[l], br[l]);
        k_init<<<(NN * HIDD + 255) / 256, 256>>>(fout, bias[l]);
        k_alpha<<<(ET + 7) / 8, 256>>>(ei, eattr, We[l], att[l]);
        k_softmax_den<<<((long long)ET * HH + 255) / 256, 256>>>(ei);
        k_aggregate<<<(ET + 7) / 8, 256>>>(ei, fout);
        float* t = fin; fin = fout; fout = t;
    }
    k_final<<<(NN + 3) / 4, 256>>>(fin, Wout, bout, y);
}

// round 2
// speedup vs baseline: 2.8644x; 2.8644x over previous
#include <cuda_runtime.h>

#define NN 50000
#define EE 800000
#define ET (EE + NN)
#define FD 128      // H*HID
#define EDD 16      // edge_dim
#define HIDD 32
#define HH 4
#define OUTD 64
#define NEGS 0.1f

// ---------------- scratch (device globals; no runtime allocation) ------------
__device__ float g_f0[NN * HIDD];          // embed out
__device__ float g_f1[NN * HIDD];          // layer0 out
__device__ float g_f2[NN * HIDD];          // layer1 out
__device__ float g_xl[(size_t)NN * FD];
__device__ float g_xr[(size_t)NN * FD];
__device__ float g_loop[NN * EDD];
__device__ float g_cnt[NN];
__device__ float g_ex[(size_t)ET * HH];    // exp(alpha) per edge-head
__device__ float g_den[2][NN * HH];        // softmax denominators (then reciprocals)

__device__ __forceinline__ float lrelu(float v) { return v > 0.f ? v : NEGS * v; }

// ---------------- one-shot init: zero loop/cnt/den, seed outputs with bias ----
__global__ void k_init_all(const float* __restrict__ bias0, const float* __restrict__ bias1) {
    int i = blockIdx.x * blockDim.x + threadIdx.x;
    if (i >= NN * HIDD) return;
    if (i < NN) g_cnt[i] = 0.f;
    if (i < NN * HH) { g_den[0][i] = 0.f; g_den[1][i] = 0.f; }
    if (i < NN * EDD) g_loop[i] = 0.f;
    g_f1[i] = bias0[i & 31];
    g_f2[i] = bias1[i & 31];
}

// ---------------- input embed: Linear(128->32) + BN(eval) + LeakyReLU --------
__global__ void k_embed(const float* __restrict__ x, const float* __restrict__ W0,
                        const float* __restrict__ b0, const float* __restrict__ bng,
                        const float* __restrict__ bnb, const float* __restrict__ bnm,
                        const float* __restrict__ bnv) {
    __shared__ float W0t[128 * 32];   // [k][j]
    int tid = threadIdx.x;
    for (int i = tid; i < 128 * 32; i += blockDim.x) {
        int k = i >> 5, j = i & 31;
        W0t[i] = W0[j * 128 + k];
    }
    __syncthreads();
    int warp = tid >> 5, lane = tid & 31;
    float sc = bng[lane] * rsqrtf(bnv[lane] + 1e-5f);
    float bb = bnb[lane], bm = bnm[lane], b00 = b0[lane];
#pragma unroll
    for (int it = 0; it < 8; it++) {
        int n = blockIdx.x * 64 + it * 8 + warp;
        if (n >= NN) return;
        const float* xr_ = x + (size_t)n * 128;
        float acc = 0.f;
#pragma unroll 8
        for (int k = 0; k < 128; k++) acc += xr_[k] * W0t[k * 32 + lane];
        acc += b00;
        acc = (acc - bm) * sc + bb;
        g_f0[n * 32 + lane] = lrelu(acc);
    }
}

// ---------------- self-loop attr: per-dst mean of edge_attr ------------------
__global__ void k_loop_accum(const int* __restrict__ ei, const float* __restrict__ ea) {
    int i = blockIdx.x * blockDim.x + threadIdx.x;
    if (i >= EE * 4) return;
    int e = i >> 2, q = i & 3;
    int dst = ei[EE + e];
    float4 v = ((const float4*)ea)[(size_t)e * 4 + q];
    float* lp = &g_loop[dst * EDD + q * 4];
    atomicAdd(lp + 0, v.x);
    atomicAdd(lp + 1, v.y);
    atomicAdd(lp + 2, v.z);
    atomicAdd(lp + 3, v.w);
    if (q == 0) atomicAdd(&g_cnt[dst], 1.f);
}
__global__ void k_loop_div() {
    int i = blockIdx.x * blockDim.x + threadIdx.x;
    if (i >= NN * 4) return;
    float inv = 1.f / fmaxf(g_cnt[i >> 2], 1.f);
    float4* lp = (float4*)g_loop;
    float4 v = lp[i];
    v.x *= inv; v.y *= inv; v.z *= inv; v.w *= inv;
    lp[i] = v;
}

// ---------------- node transforms: xl = f@Wl^T+bl, xr = f@Wr^T+br ------------
__global__ void k_xlxr(const float* __restrict__ feat,
                       const float* __restrict__ Wl, const float* __restrict__ bl,
                       const float* __restrict__ Wr, const float* __restrict__ br) {
    __shared__ float WlT[32 * 128];
    __shared__ float WrT[32 * 128];
    int tid = threadIdx.x;
    for (int i = tid; i < 32 * 128; i += blockDim.x) {
        int k = i >> 7, j = i & 127;
        WlT[i] = Wl[j * 32 + k];
        WrT[i] = Wr[j * 32 + k];
    }
    __syncthreads();
    int j = tid & 127;
    float blj = bl[j], brj = br[j];
#pragma unroll
    for (int it = 0; it < 16; it++) {
        int n = blockIdx.x * 32 + it * 2 + (tid >> 7);
        if (n >= NN) return;
        const float* fr = feat + n * 32;
        float al = 0.f, ar = 0.f;
#pragma unroll
        for (int k = 0; k < 32; k++) {
            float fv = fr[k];
            al += fv * WlT[k * 128 + j];
            ar += fv * WrT[k * 128 + j];
        }
        g_xl[(size_t)n * 128 + j] = al + blj;
        g_xr[(size_t)n * 128 + j] = ar + brj;
    }
}

// ---------------- pass A: alpha -> exp (no max shift) + denominator ----------
__global__ void k_alpha(const int* __restrict__ ei, const float* __restrict__ eattr,
                        const float* __restrict__ We, const float* __restrict__ att,
                        float* __restrict__ den) {
    __shared__ float WeT[16 * 128];   // [d][j]
    __shared__ float attS[128];
    int tid = threadIdx.x;
    for (int i = tid; i < 16 * 128; i += blockDim.x) {
        int d = i >> 7, j = i & 127;
        WeT[i] = We[j * 16 + d];
    }
    if (tid < 128) attS[tid] = att[tid];
    __syncthreads();
    int warp = tid >> 5, lane = tid & 31;
    int base = blockIdx.x * 64;
#pragma unroll
    for (int it = 0; it < 8; it++) {
        int e = base + it * 8 + warp;
        if (e >= ET) return;
        int src, dst;
        float eav = 0.f;
        if (e < EE) {
            src = ei[e]; dst = ei[EE + e];
            if (lane < 16) eav = eattr[(size_t)e * 16 + lane];
        } else {
            src = dst = e - EE;
            if (lane < 16) eav = g_loop[(e - EE) * 16 + lane];
        }
        const float* xls = g_xl + (size_t)src * 128;
        const float* xrd = g_xr + (size_t)dst * 128;
        float xlv0 = xls[lane],      xrv0 = xrd[lane];
        float xlv1 = xls[32 + lane], xrv1 = xrd[32 + lane];
        float xlv2 = xls[64 + lane], xrv2 = xrd[64 + lane];
        float xlv3 = xls[96 + lane], xrv3 = xrd[96 + lane];
        float e0 = 0.f, e1 = 0.f, e2 = 0.f, e3 = 0.f;
#pragma unroll
        for (int d = 0; d < 16; d++) {
            float ev = __shfl_sync(0xffffffffu, eav, d);
            const float* w = &WeT[d * 128 + lane];
            e0 += ev * w[0];
            e1 += ev * w[32];
            e2 += ev * w[64];
            e3 += ev * w[96];
        }
        float a0 = lrelu(xlv0 + xrv0 + e0) * attS[lane];
        float a1 = lrelu(xlv1 + xrv1 + e1) * attS[32 + lane];
        float a2 = lrelu(xlv2 + xrv2 + e2) * attS[64 + lane];
        float a3 = lrelu(xlv3 + xrv3 + e3) * attS[96 + lane];
#pragma unroll
        for (int off = 16; off; off >>= 1) {
            a0 += __shfl_xor_sync(0xffffffffu, a0, off);
            a1 += __shfl_xor_sync(0xffffffffu, a1, off);
            a2 += __shfl_xor_sync(0xffffffffu, a2, off);
            a3 += __shfl_xor_sync(0xffffffffu, a3, off);
        }
        if (lane < 4) {
            float mine = (lane == 0) ? a0 : (lane == 1) ? a1 : (lane == 2) ? a2 : a3;
            float ex = __expf(mine);
            g_ex[(size_t)e * 4 + lane] = ex;
            atomicAdd(&den[dst * 4 + lane], ex);
        }
    }
}

// ---------------- reciprocal of denominators ---------------------------------
__global__ void k_rcp(float* __restrict__ den) {
    int i = blockIdx.x * blockDim.x + threadIdx.x;
    if (i < NN * HH) den[i] = 1.f / den[i];
}

// ---------------- pass C: weighted aggregate (mean over heads folded in) -----
__global__ void k_aggregate(const int* __restrict__ ei, const float* __restrict__ den,
                            float* __restrict__ outbuf) {
    int tid = threadIdx.x;
    int warp = tid >> 5, lane = tid & 31;
    int base = blockIdx.x * 64;
#pragma unroll
    for (int it = 0; it < 8; it++) {
        int e = base + it * 8 + warp;
        if (e >= ET) return;
        int src, dst;
        if (e < EE) { src = ei[e]; dst = ei[EE + e]; }
        else        { src = dst = e - EE; }
        float w = 0.f;
        if (lane < 4) w = g_ex[(size_t)e * 4 + lane] * den[dst * 4 + lane];
        float w0 = __shfl_sync(0xffffffffu, w, 0);
        float w1 = __shfl_sync(0xffffffffu, w, 1);
        float w2 = __shfl_sync(0xffffffffu, w, 2);
        float w3 = __shfl_sync(0xffffffffu, w, 3);
        const float* xls = g_xl + (size_t)src * 128;
        float acc = 0.25f * (w0 * xls[lane] + w1 * xls[32 + lane] +
                             w2 * xls[64 + lane] + w3 * xls[96 + lane]);
        atomicAdd(&outbuf[dst * 32 + lane], acc);
    }
}

// ---------------- output head: Linear(32->64) + LeakyReLU --------------------
__global__ void k_final(const float* __restrict__ feat, const float* __restrict__ Wout,
                        const float* __restrict__ bout, float* __restrict__ y) {
    __shared__ float WT[32 * 64];   // [c][o]
    int tid = threadIdx.x;
    for (int i = tid; i < 32 * 64; i += blockDim.x) {
        int c = i >> 6, o = i & 63;
        WT[i] = Wout[o * 32 + c];
    }
    __syncthreads();
    int o = tid & 63;
    float bo = bout[o];
#pragma unroll
    for (int it = 0; it < 16; it++) {
        int n = blockIdx.x * 64 + it * 4 + (tid >> 6);
        if (n >= NN) return;
        const float* fr = feat + n * 32;
        float acc = 0.f;
#pragma unroll
        for (int c = 0; c < 32; c++) acc += fr[c] * WT[c * 64 + o];
        acc += bo;
        y[(size_t)n * 64 + o] = lrelu(acc);
    }
}

// =============================================================================
extern "C" void kernel_launch(void* const* d_in, const int* in_sizes, int n_in,
                              void* d_out, int out_size) {
    const float* x     = (const float*)d_in[0];
    const int*   ei    = (const int*)d_in[1];
    const float* eattr = (const float*)d_in[2];
    const float* W0    = (const float*)d_in[3];
    const float* b0    = (const float*)d_in[4];
    const float* bng   = (const float*)d_in[5];
    const float* bnb   = (const float*)d_in[6];
    const float* bnm   = (const float*)d_in[7];
    const float* bnv   = (const float*)d_in[8];
    const float* Wl[2]   = {(const float*)d_in[9],  (const float*)d_in[16]};
    const float* bl[2]   = {(const float*)d_in[10], (const float*)d_in[17]};
    const float* Wr[2]   = {(const float*)d_in[11], (const float*)d_in[18]};
    const float* br[2]   = {(const float*)d_in[12], (const float*)d_in[19]};
    const float* We[2]   = {(const float*)d_in[13], (const float*)d_in[20]};
    const float* att[2]  = {(const float*)d_in[14], (const float*)d_in[21]};
    const float* bias[2] = {(const float*)d_in[15], (const float*)d_in[22]};
    const float* Wout  = (const float*)d_in[23];
    const float* bout  = (const float*)d_in[24];
    float* y = (float*)d_out;

    float *f0, *f1, *f2, *den0, *den1;
    cudaGetSymbolAddress((void**)&f0, g_f0);
    cudaGetSymbolAddress((void**)&f1, g_f1);
    cudaGetSymbolAddress((void**)&f2, g_f2);
    cudaGetSymbolAddress((void**)&den0, g_den);
    den1 = den0 + NN * HH;

    // launch order chosen so ncu (-s 5 -c 1) profiles k_alpha
    k_embed<<<(NN + 63) / 64, 256>>>(x, W0, b0, bng, bnb, bnm, bnv);       // 0
    k_init_all<<<(NN * HIDD + 255) / 256, 256>>>(bias[0], bias[1]);        // 1
    k_loop_accum<<<(EE * 4 + 255) / 256, 256>>>(ei, eattr);                // 2
    k_loop_div<<<(NN * 4 + 255) / 256, 256>>>();                           // 3

    const float* fin[3]  = {f0, f1, f2};
    float*       fden[2] = {den0, den1};
    float*       fout[2] = {f1, f2};
    for (int l = 0; l < 2; l++) {
        k_xlxr<<<(NN + 31) / 32, 256>>>(fin[l], Wl[l], bl[l], Wr[l], br[l]);   // 4, 8
        k_alpha<<<(ET + 63) / 64, 256>>>(ei, eattr, We[l], att[l], fden[l]);   // 5, 9
        k_rcp<<<(NN * HH + 255) / 256, 256>>>(fden[l]);                        // 6, 10
        k_aggregate<<<(ET + 63) / 64, 256>>>(ei, fden[l], fout[l]);            // 7, 11
    }
    k_final<<<(NN + 63) / 64, 256>>>(f2, Wout, bout, y);                       // 12
}

// round 4
// speedup vs baseline: 3.8086x; 1.3296x over previous
#include <cuda_runtime.h>

#define NN 50000
#define EE 800000
#define ET (EE + NN)
#define FD 128      // H*HID
#define EDD 16      // edge_dim
#define HIDD 32
#define HH 4
#define OUTD 64
#define NEGS 0.1f

// ---------------- scratch (device globals) -----------------------------------
__device__ float g_f0[NN * HIDD];
__device__ float g_f1[NN * HIDD];
__device__ float g_f2[NN * HIDD];
__device__ float g_xl[(size_t)NN * FD];
__device__ float g_xr[(size_t)NN * FD];
__device__ float g_loop[NN * EDD];
__device__ float g_cnt[NN];
__device__ float g_ex[(size_t)ET * HH];
__device__ float g_den[2][NN * HH];

__device__ __forceinline__ float lrelu(float v) { return v > 0.f ? v : NEGS * v; }

// ------ launch 0: embed + zero loop/cnt/den + seed outputs with bias ---------
__global__ void k_embed_plus(const float* __restrict__ x, const float* __restrict__ W0,
                             const float* __restrict__ b0, const float* __restrict__ bng,
                             const float* __restrict__ bnb, const float* __restrict__ bnm,
                             const float* __restrict__ bnv,
                             const float* __restrict__ bias0, const float* __restrict__ bias1) {
    __shared__ float W0t[128 * 32];   // [k][j]
    int tid = threadIdx.x;
    for (int i = tid; i < 128 * 32; i += blockDim.x) {
        int k = i >> 5, j = i & 31;
        W0t[i] = W0[j * 128 + k];
    }
    __syncthreads();
    int warp = tid >> 5, lane = tid & 31;
    float sc = bng[lane] * rsqrtf(bnv[lane] + 1e-5f);
    float bb = bnb[lane], bm = bnm[lane], b00 = b0[lane];
#pragma unroll
    for (int it = 0; it < 8; it++) {
        int n = blockIdx.x * 64 + it * 8 + warp;
        if (n < NN) {
            const float* xr_ = x + (size_t)n * 128;
            float acc = 0.f;
#pragma unroll 8
            for (int k = 0; k < 128; k++) acc += xr_[k] * W0t[k * 32 + lane];
            acc += b00;
            acc = (acc - bm) * sc + bb;
            g_f0[n * 32 + lane] = lrelu(acc);
        }
    }
    // side work: zero accumulators (required for per-call idempotency)
    int gs = blockIdx.x * blockDim.x + tid;
    int stride = gridDim.x * blockDim.x;
    float4 z4 = make_float4(0.f, 0.f, 0.f, 0.f);
    for (int i = gs; i < NN * 4; i += stride) ((float4*)g_loop)[i] = z4;
    for (int i = gs; i < NN; i += stride) g_cnt[i] = 0.f;
    for (int i = gs; i < NN * HH; i += stride) { g_den[0][i] = 0.f; g_den[1][i] = 0.f; }
    for (int i = gs; i < NN * HIDD; i += stride) {
        g_f1[i] = bias0[i & 31];
        g_f2[i] = bias1[i & 31];
    }
}

// ------ launch 1: self-loop attr accumulation ---------------------------------
__global__ void k_loop_accum(const int* __restrict__ ei, const float* __restrict__ ea) {
    int i = blockIdx.x * blockDim.x + threadIdx.x;
    if (i >= EE * 4) return;
    int e = i >> 2, q = i & 3;
    int dst = ei[EE + e];
    float4 v = ((const float4*)ea)[(size_t)e * 4 + q];
    float* lp = &g_loop[dst * EDD + q * 4];
    atomicAdd(lp + 0, v.x);
    atomicAdd(lp + 1, v.y);
    atomicAdd(lp + 2, v.z);
    atomicAdd(lp + 3, v.w);
    if (q == 0) atomicAdd(&g_cnt[dst], 1.f);
}

// ------ node transforms, loop-swapped (weights in regs) -----------------------
__global__ void k_xlxr(const float* __restrict__ feat,
                       const float* __restrict__ Wl, const float* __restrict__ bl,
                       const float* __restrict__ Wr, const float* __restrict__ br) {
    __shared__ float WlT[32 * 128];
    __shared__ float WrT[32 * 128];
    __shared__ float tile[32 * 32];
    int tid = threadIdx.x;
    for (int i = tid; i < 32 * 128; i += blockDim.x) {
        int k = i >> 7, j = i & 127;
        WlT[i] = Wl[j * 32 + k];
        WrT[i] = Wr[j * 32 + k];
    }
    int nbase = blockIdx.x * 32;
    for (int i = tid; i < 32 * 32; i += blockDim.x) {
        int n = nbase + (i >> 5);
        tile[i] = (n < NN) ? feat[n * 32 + (i & 31)] : 0.f;
    }
    __syncthreads();
    int j = tid & 127;
    int half = tid >> 7;
    float accl[16], accr[16];
#pragma unroll
    for (int n = 0; n < 16; n++) { accl[n] = 0.f; accr[n] = 0.f; }
#pragma unroll
    for (int k = 0; k < 32; k++) {
        float wl = WlT[k * 128 + j];
        float wr = WrT[k * 128 + j];
        const float* tr = &tile[(half * 16) * 32 + k];
#pragma unroll
        for (int n = 0; n < 16; n++) {
            float fv = tr[n * 32];
            accl[n] += fv * wl;
            accr[n] += fv * wr;
        }
    }
    float blj = bl[j], brj = br[j];
#pragma unroll
    for (int n = 0; n < 16; n++) {
        int node = nbase + half * 16 + n;
        if (node < NN) {
            g_xl[(size_t)node * 128 + j] = accl[n] + blj;
            g_xr[(size_t)node * 128 + j] = accr[n] + brj;
        }
    }
}

// ------ pass A: 8-edge tiles per warp; self-loop mean folded in ---------------
__global__ void k_alpha(const int* __restrict__ ei, const float* __restrict__ eattr,
                        const float* __restrict__ We, const float* __restrict__ att,
                        float* __restrict__ den) {
    __shared__ float WeS[16 * 128];   // [d][j]
    __shared__ float attS[128];
    int tid = threadIdx.x;
    for (int i = tid; i < 16 * 128; i += blockDim.x) {
        int d = i >> 7, j = i & 127;
        WeS[i] = We[j * 16 + d];
    }
    if (tid < 128) attS[tid] = att[tid];
    __syncthreads();
    int warp = tid >> 5, lane = tid & 31;
    int e0 = (blockIdx.x * 8 + warp) * 8;
    if (e0 >= ET) return;

    // lanes 0-7: src of edge e0+lane; lanes 8-15: dst of edge e0+(lane-8)
    int sreg = 0, dreg = 0;
    {
        int le = e0 + (lane & 7);
        if (le < ET) {
            if (lane < 8)       sreg = (le < EE) ? ei[le]      : le - EE;
            else if (lane < 16) dreg = (le < EE) ? ei[EE + le] : le - EE;
        }
    }
    // eattr for 8 edges: lane -> (edge = lane>>2, quad = lane&3)
    float4 ea4 = make_float4(0.f, 0.f, 0.f, 0.f);
    {
        int ee = e0 + (lane >> 2);
        if (ee < EE) {
            ea4 = ((const float4*)eattr)[(size_t)ee * 4 + (lane & 3)];
        } else if (ee < ET) {
            int n = ee - EE;
            ea4 = ((const float4*)g_loop)[(size_t)n * 4 + (lane & 3)];
            float inv = 1.f / fmaxf(g_cnt[n], 1.f);
            ea4.x *= inv; ea4.y *= inv; ea4.z *= inv; ea4.w *= inv;
        }
    }
    float eav[4] = {ea4.x, ea4.y, ea4.z, ea4.w};

    float a0[8], a1[8], a2[8], a3[8];
#pragma unroll
    for (int e = 0; e < 8; e++) { a0[e] = 0.f; a1[e] = 0.f; a2[e] = 0.f; a3[e] = 0.f; }
#pragma unroll
    for (int d = 0; d < 16; d++) {
        float w0 = WeS[d * 128 + lane];
        float w1 = WeS[d * 128 + 32 + lane];
        float w2 = WeS[d * 128 + 64 + lane];
        float w3 = WeS[d * 128 + 96 + lane];
        float evsrc = eav[d & 3];
#pragma unroll
        for (int e = 0; e < 8; e++) {
            float ev = __shfl_sync(0xffffffffu, evsrc, e * 4 + (d >> 2));
            a0[e] += ev * w0;
            a1[e] += ev * w1;
            a2[e] += ev * w2;
            a3[e] += ev * w3;
        }
    }
    float at0 = attS[lane], at1 = attS[32 + lane], at2 = attS[64 + lane], at3 = attS[96 + lane];
#pragma unroll
    for (int e = 0; e < 8; e++) {
        int me = e0 + e;
        if (me >= ET) break;
        int se = __shfl_sync(0xffffffffu, sreg, e);
        int de = __shfl_sync(0xffffffffu, dreg, 8 + e);
        const float* xls = g_xl + (size_t)se * 128;
        const float* xrd = g_xr + (size_t)de * 128;
        float m0 = lrelu(xls[lane]      + xrd[lane]      + a0[e]) * at0;
        float m1 = lrelu(xls[32 + lane] + xrd[32 + lane] + a1[e]) * at1;
        float m2 = lrelu(xls[64 + lane] + xrd[64 + lane] + a2[e]) * at2;
        float m3 = lrelu(xls[96 + lane] + xrd[96 + lane] + a3[e]) * at3;
#pragma unroll
        for (int off = 16; off; off >>= 1) {
            m0 += __shfl_xor_sync(0xffffffffu, m0, off);
            m1 += __shfl_xor_sync(0xffffffffu, m1, off);
            m2 += __shfl_xor_sync(0xffffffffu, m2, off);
            m3 += __shfl_xor_sync(0xffffffffu, m3, off);
        }
        if (lane < 4) {
            float v = (lane == 0) ? m0 : (lane == 1) ? m1 : (lane == 2) ? m2 : m3;
            float ex = __expf(v);
            g_ex[(size_t)me * 4 + lane] = ex;
            atomicAdd(&den[de * 4 + lane], ex);
        }
    }
}

// ------ reciprocal of denominators --------------------------------------------
__global__ void k_rcp(float* __restrict__ den) {
    int i = blockIdx.x * blockDim.x + threadIdx.x;
    if (i < NN * HH) den[i] = 1.f / den[i];
}

// ------ pass C: weighted aggregate (head-mean folded) --------------------------
__global__ void k_aggregate(const int* __restrict__ ei, const float* __restrict__ den,
                            float* __restrict__ outbuf) {
    int tid = threadIdx.x;
    int warp = tid >> 5, lane = tid & 31;
    int base = blockIdx.x * 64;
#pragma unroll
    for (int it = 0; it < 8; it++) {
        int e = base + it * 8 + warp;
        if (e >= ET) return;
        int src, dst;
        if (e < EE) { src = ei[e]; dst = ei[EE + e]; }
        else        { src = dst = e - EE; }
        float w = 0.f;
        if (lane < 4) w = g_ex[(size_t)e * 4 + lane] * den[dst * 4 + lane];
        float w0 = __shfl_sync(0xffffffffu, w, 0);
        float w1 = __shfl_sync(0xffffffffu, w, 1);
        float w2 = __shfl_sync(0xffffffffu, w, 2);
        float w3 = __shfl_sync(0xffffffffu, w, 3);
        const float* xls = g_xl + (size_t)src * 128;
        float acc = 0.25f * (w0 * xls[lane] + w1 * xls[32 + lane] +
                             w2 * xls[64 + lane] + w3 * xls[96 + lane]);
        atomicAdd(&outbuf[dst * 32 + lane], acc);
    }
}

// ------ output head -------------------------------------------------------------
__global__ void k_final(const float* __restrict__ feat, const float* __restrict__ Wout,
                        const float* __restrict__ bout, float* __restrict__ y) {
    __shared__ float WT[32 * 64];   // [c][o]
    int tid = threadIdx.x;
    for (int i = tid; i < 32 * 64; i += blockDim.x) {
        int c = i >> 6, o = i & 63;
        WT[i] = Wout[o * 32 + c];
    }
    __syncthreads();
    int o = tid & 63;
    float bo = bout[o];
#pragma unroll
    for (int it = 0; it < 16; it++) {
        int n = blockIdx.x * 64 + it * 4 + (tid >> 6);
        if (n >= NN) return;
        const float* fr = feat + n * 32;
        float acc = 0.f;
#pragma unroll
        for (int c = 0; c < 32; c++) acc += fr[c] * WT[c * 64 + o];
        acc += bo;
        y[(size_t)n * 64 + o] = lrelu(acc);
    }
}

// =============================================================================
extern "C" void kernel_launch(void* const* d_in, const int* in_sizes, int n_in,
                              void* d_out, int out_size) {
    const float* x     = (const float*)d_in[0];
    const int*   ei    = (const int*)d_in[1];
    const float* eattr = (const float*)d_in[2];
    const float* W0    = (const float*)d_in[3];
    const float* b0    = (const float*)d_in[4];
    const float* bng   = (const float*)d_in[5];
    const float* bnb   = (const float*)d_in[6];
    const float* bnm   = (const float*)d_in[7];
    const float* bnv   = (const float*)d_in[8];
    const float* Wl[2]   = {(const float*)d_in[9],  (const float*)d_in[16]};
    const float* bl[2]   = {(const float*)d_in[10], (const float*)d_in[17]};
    const float* Wr[2]   = {(const float*)d_in[11], (const float*)d_in[18]};
    const float* br[2]   = {(const float*)d_in[12], (const float*)d_in[19]};
    const float* We[2]   = {(const float*)d_in[13], (const float*)d_in[20]};
    const float* att[2]  = {(const float*)d_in[14], (const float*)d_in[21]};
    const float* bias[2] = {(const float*)d_in[15], (const float*)d_in[22]};
    const float* Wout  = (const float*)d_in[23];
    const float* bout  = (const float*)d_in[24];
    float* y = (float*)d_out;

    float *f0, *f1, *f2, *den0, *den1;
    cudaGetSymbolAddress((void**)&f0, g_f0);
    cudaGetSymbolAddress((void**)&f1, g_f1);
    cudaGetSymbolAddress((void**)&f2, g_f2);
    cudaGetSymbolAddress((void**)&den0, g_den);
    den1 = den0 + NN * HH;

    k_embed_plus<<<(NN + 63) / 64, 256>>>(x, W0, b0, bng, bnb, bnm, bnv,
                                          bias[0], bias[1]);                         // 0
    k_loop_accum<<<(EE * 4 + 255) / 256, 256>>>(ei, eattr);                          // 1

    const float* fin[2]  = {f0, f1};
    float*       fden[2] = {den0, den1};
    float*       fout[2] = {f1, f2};
    for (int l = 0; l < 2; l++) {
        k_xlxr<<<(NN + 31) / 32, 256>>>(fin[l], Wl[l], bl[l], Wr[l], br[l]);         // 2, 6
        k_alpha<<<(ET + 63) / 64, 256>>>(ei, eattr, We[l], att[l], fden[l]);         // 3 <- profiled, 7
        k_rcp<<<(NN * HH + 255) / 256, 256>>>(fden[l]);                              // 4, 8
        k_aggregate<<<(ET + 63) / 64, 256>>>(ei, fden[l], fout[l]);                  // 5, 9
    }
    k_final<<<(NN + 63) / 64, 256>>>(f2, Wout, bout, y);                             // 10
}

// round 5
// speedup vs baseline: 4.1618x; 1.0927x over previous
#include <cuda_runtime.h>

#define NN 50000
#define EE 800000
#define ET (EE + NN)
#define FD 128      // H*HID
#define EDD 16      // edge_dim
#define HIDD 32
#define HH 4
#define OUTD 64
#define NEGS 0.1f

typedef unsigned long long ull;

// ---------------- scratch (device globals) -----------------------------------
__device__ float g_f0[NN * HIDD];
__device__ float g_f1[NN * HIDD];
__device__ float g_f2[NN * HIDD];
__device__ float g_xl[(size_t)NN * FD];
__device__ float g_xr[(size_t)NN * FD];
__device__ float g_loop[NN * EDD];
__device__ float g_cnt[NN];
__device__ float g_ex[(size_t)ET * HH];
__device__ float g_den[2][NN * HH];

__device__ __forceinline__ float lrelu(float v) { return fmaxf(v, NEGS * v); }

__device__ __forceinline__ void fma2(ull& acc, ull a, ull b) {
    asm("fma.rn.f32x2 %0, %1, %2, %0;" : "+l"(acc) : "l"(a), "l"(b));
}
__device__ __forceinline__ float2 upk(ull v) {
    float2 r; asm("mov.b64 {%0,%1}, %2;" : "=f"(r.x), "=f"(r.y) : "l"(v)); return r;
}
__device__ __forceinline__ void red4(float* addr, float4 v) {
    asm volatile("red.global.add.v4.f32 [%0], {%1,%2,%3,%4};"
                 :: "l"(addr), "f"(v.x), "f"(v.y), "f"(v.z), "f"(v.w) : "memory");
}

// ------ launch 0: embed + zero loop/cnt/den + seed outputs with bias ---------
__global__ void k_embed_plus(const float* __restrict__ x, const float* __restrict__ W0,
                             const float* __restrict__ b0, const float* __restrict__ bng,
                             const float* __restrict__ bnb, const float* __restrict__ bnm,
                             const float* __restrict__ bnv,
                             const float* __restrict__ bias0, const float* __restrict__ bias1) {
    __shared__ float W0t[128 * 32];   // [k][j]
    int tid = threadIdx.x;
    for (int i = tid; i < 128 * 32; i += blockDim.x) {
        int k = i >> 5, j = i & 31;
        W0t[i] = W0[j * 128 + k];
    }
    __syncthreads();
    int warp = tid >> 5, lane = tid & 31;
    float sc = bng[lane] * rsqrtf(bnv[lane] + 1e-5f);
    float bb = bnb[lane], bm = bnm[lane], b00 = b0[lane];
#pragma unroll
    for (int it = 0; it < 8; it++) {
        int n = blockIdx.x * 64 + it * 8 + warp;
        if (n < NN) {
            const float* xr_ = x + (size_t)n * 128;
            float acc = 0.f;
#pragma unroll 8
            for (int k = 0; k < 128; k++) acc += xr_[k] * W0t[k * 32 + lane];
            acc += b00;
            acc = (acc - bm) * sc + bb;
            g_f0[n * 32 + lane] = lrelu(acc);
        }
    }
    int gs = blockIdx.x * blockDim.x + tid;
    int stride = gridDim.x * blockDim.x;
    float4 z4 = make_float4(0.f, 0.f, 0.f, 0.f);
    for (int i = gs; i < NN * 4; i += stride) ((float4*)g_loop)[i] = z4;
    for (int i = gs; i < NN; i += stride) g_cnt[i] = 0.f;
    for (int i = gs; i < NN * HH; i += stride) { g_den[0][i] = 0.f; g_den[1][i] = 0.f; }
    for (int i = gs; i < NN * HIDD; i += stride) {
        g_f1[i] = bias0[i & 31];
        g_f2[i] = bias1[i & 31];
    }
}

// ------ launch 1: self-loop attr accumulation (vectorized reds) ---------------
__global__ void k_loop_accum(const int* __restrict__ ei, const float* __restrict__ ea) {
    int i = blockIdx.x * blockDim.x + threadIdx.x;
    if (i >= EE * 4) return;
    int e = i >> 2, q = i & 3;
    int dst = ei[EE + e];
    float4 v = ((const float4*)ea)[i];
    red4(&g_loop[dst * EDD + q * 4], v);
    if (q == 0) atomicAdd(&g_cnt[dst], 1.f);
}

// ------ node transforms, loop-swapped (weights in regs) -----------------------
__global__ void k_xlxr(const float* __restrict__ feat,
                       const float* __restrict__ Wl, const float* __restrict__ bl,
                       const float* __restrict__ Wr, const float* __restrict__ br) {
    __shared__ float WlT[32 * 128];
    __shared__ float WrT[32 * 128];
    __shared__ float tile[32 * 32];
    int tid = threadIdx.x;
    for (int i = tid; i < 32 * 128; i += blockDim.x) {
        int k = i >> 7, j = i & 127;
        WlT[i] = Wl[j * 32 + k];
        WrT[i] = Wr[j * 32 + k];
    }
    int nbase = blockIdx.x * 32;
    for (int i = tid; i < 32 * 32; i += blockDim.x) {
        int n = nbase + (i >> 5);
        tile[i] = (n < NN) ? feat[n * 32 + (i & 31)] : 0.f;
    }
    __syncthreads();
    int j = tid & 127;
    int half = tid >> 7;
    float accl[16], accr[16];
#pragma unroll
    for (int n = 0; n < 16; n++) { accl[n] = 0.f; accr[n] = 0.f; }
#pragma unroll
    for (int k = 0; k < 32; k++) {
        float wl = WlT[k * 128 + j];
        float wr = WrT[k * 128 + j];
        const float* tr = &tile[(half * 16) * 32 + k];
#pragma unroll
        for (int n = 0; n < 16; n++) {
            float fv = tr[n * 32];
            accl[n] += fv * wl;
            accr[n] += fv * wr;
        }
    }
    float blj = bl[j], brj = br[j];
#pragma unroll
    for (int n = 0; n < 16; n++) {
        int node = nbase + half * 16 + n;
        if (node < NN) {
            g_xl[(size_t)node * 128 + j] = accl[n] + blj;
            g_xr[(size_t)node * 128 + j] = accr[n] + brj;
        }
    }
}

// ------ pass A: float4 channel layout, FFMA2 EA, smem-bcast eattr -------------
// lane owns channels 4l..4l+3 (head = l>>3); warp does 8 edges.
__global__ void k_alpha(const int* __restrict__ ei, const float* __restrict__ eattr,
                        const float* __restrict__ We, const float* __restrict__ att,
                        float* __restrict__ den) {
    __shared__ float WeS[16 * 128];            // [d][channel]
    __shared__ float2 evsp[8][8][16];          // [warp][edge][d] splat (v,v)
    int tid = threadIdx.x;
    for (int i = tid; i < 16 * 128; i += blockDim.x) {
        int d = i >> 7, j = i & 127;
        WeS[i] = We[j * 16 + d];
    }
    __syncthreads();
    int warp = tid >> 5, lane = tid & 31;
    int e0 = (blockIdx.x * 8 + warp) * 8;
    if (e0 >= ET) return;

    float4 att4 = ((const float4*)att)[lane];

    // edge indices: lanes 0-7 src, lanes 8-15 dst
    int sreg = 0, dreg = 0;
    {
        int le = e0 + (lane & 7);
        if (le < ET) {
            if (lane < 8)       sreg = (le < EE) ? ei[le]      : le - EE;
            else if (lane < 16) dreg = (le < EE) ? ei[EE + le] : le - EE;
        }
    }
    // stage eattr splats: lane -> edge = lane>>2, dims 4q..4q+3 (q = lane&3)
    {
        float4 ea4 = make_float4(0.f, 0.f, 0.f, 0.f);
        int ee = e0 + (lane >> 2);
        if (ee < EE) {
            ea4 = ((const float4*)eattr)[(size_t)ee * 4 + (lane & 3)];
        } else if (ee < ET) {
            int n = ee - EE;
            ea4 = ((const float4*)g_loop)[(size_t)n * 4 + (lane & 3)];
            float inv = 1.f / fmaxf(g_cnt[n], 1.f);
            ea4.x *= inv; ea4.y *= inv; ea4.z *= inv; ea4.w *= inv;
        }
        float2* myev = &evsp[warp][lane >> 2][(lane & 3) * 4];
        myev[0] = make_float2(ea4.x, ea4.x);
        myev[1] = make_float2(ea4.y, ea4.y);
        myev[2] = make_float2(ea4.z, ea4.z);
        myev[3] = make_float2(ea4.w, ea4.w);
    }
    __syncwarp();

    // EA accumulation: acc[e] packed as 2x f32x2
    ull acc01[8], acc23[8];
#pragma unroll
    for (int e = 0; e < 8; e++) { acc01[e] = 0ull; acc23[e] = 0ull; }
#pragma unroll
    for (int dp = 0; dp < 8; dp++) {
        ulonglong2 wa = *(const ulonglong2*)&WeS[(2 * dp) * 128 + 4 * lane];
        ulonglong2 wb = *(const ulonglong2*)&WeS[(2 * dp + 1) * 128 + 4 * lane];
#pragma unroll
        for (int e = 0; e < 8; e++) {
            ulonglong2 ev = *(const ulonglong2*)&evsp[warp][e][2 * dp];  // (vd,vd),(vd1,vd1)
            fma2(acc01[e], ev.x, wa.x);
            fma2(acc23[e], ev.x, wa.y);
            fma2(acc01[e], ev.y, wb.x);
            fma2(acc23[e], ev.y, wb.y);
        }
    }

#pragma unroll
    for (int e = 0; e < 8; e++) {
        int me = e0 + e;
        if (me >= ET) break;
        int se = __shfl_sync(0xffffffffu, sreg, e);
        int de = __shfl_sync(0xffffffffu, dreg, 8 + e);
        float4 xl4 = ((const float4*)(g_xl + (size_t)se * 128))[lane];
        float4 xr4 = ((const float4*)(g_xr + (size_t)de * 128))[lane];
        float2 a = upk(acc01[e]);
        float2 b = upk(acc23[e]);
        float t0 = lrelu(xl4.x + xr4.x + a.x) * att4.x;
        float t1 = lrelu(xl4.y + xr4.y + a.y) * att4.y;
        float t2 = lrelu(xl4.z + xr4.z + b.x) * att4.z;
        float t3 = lrelu(xl4.w + xr4.w + b.y) * att4.w;
        float s = (t0 + t1) + (t2 + t3);
        s += __shfl_xor_sync(0xffffffffu, s, 1);
        s += __shfl_xor_sync(0xffffffffu, s, 2);
        s += __shfl_xor_sync(0xffffffffu, s, 4);
        if ((lane & 7) == 0) {
            int h = lane >> 3;
            float ex = __expf(s);
            g_ex[(size_t)me * 4 + h] = ex;
            atomicAdd(&den[de * 4 + h], ex);
        }
    }
}

// ------ reciprocal of denominators (0.25 head-mean folded in) ------------------
__global__ void k_rcp(float* __restrict__ den) {
    int i = blockIdx.x * blockDim.x + threadIdx.x;
    if (i < NN * HH) den[i] = 0.25f / den[i];
}

// ------ pass C: weighted aggregate, float4 gather + v4 reductions --------------
__global__ void k_aggregate(const int* __restrict__ ei, const float* __restrict__ den,
                            float* __restrict__ outbuf) {
    int tid = threadIdx.x;
    int warp = tid >> 5, lane = tid & 31;
    int e0 = (blockIdx.x * 8 + warp) * 8;
    if (e0 >= ET) return;
    int sreg = 0, dreg = 0;
    {
        int le = e0 + (lane & 7);
        if (le < ET) {
            if (lane < 8)       sreg = (le < EE) ? ei[le]      : le - EE;
            else if (lane < 16) dreg = (le < EE) ? ei[EE + le] : le - EE;
        }
    }
#pragma unroll
    for (int e = 0; e < 8; e++) {
        int me = e0 + e;
        if (me >= ET) break;
        int se = __shfl_sync(0xffffffffu, sreg, e);
        int de = __shfl_sync(0xffffffffu, dreg, 8 + e);
        float w = 0.f;
        if (lane < 4) w = g_ex[(size_t)me * 4 + lane] * den[de * 4 + lane];  // den holds 0.25/sum
        float wl = __shfl_sync(0xffffffffu, w, lane >> 3);
        float4 xl4 = ((const float4*)(g_xl + (size_t)se * 128))[lane];
        float4 p;
        p.x = wl * xl4.x; p.y = wl * xl4.y; p.z = wl * xl4.z; p.w = wl * xl4.w;
        p.x += __shfl_xor_sync(0xffffffffu, p.x, 8);
        p.y += __shfl_xor_sync(0xffffffffu, p.y, 8);
        p.z += __shfl_xor_sync(0xffffffffu, p.z, 8);
        p.w += __shfl_xor_sync(0xffffffffu, p.w, 8);
        p.x += __shfl_xor_sync(0xffffffffu, p.x, 16);
        p.y += __shfl_xor_sync(0xffffffffu, p.y, 16);
        p.z += __shfl_xor_sync(0xffffffffu, p.z, 16);
        p.w += __shfl_xor_sync(0xffffffffu, p.w, 16);
        if (lane < 8) red4(&outbuf[de * 32 + 4 * lane], p);
    }
}

// ------ output head -------------------------------------------------------------
__global__ void k_final(const float* __restrict__ feat, const float* __restrict__ Wout,
                        const float* __restrict__ bout, float* __restrict__ y) {
    __shared__ float WT[32 * 64];   // [c][o]
    int tid = threadIdx.x;
    for (int i = tid; i < 32 * 64; i += blockDim.x) {
        int c = i >> 6, o = i & 63;
        WT[i] = Wout[o * 32 + c];
    }
    __syncthreads();
    int o = tid & 63;
    float bo = bout[o];
#pragma unroll
    for (int it = 0; it < 16; it++) {
        int n = blockIdx.x * 64 + it * 4 + (tid >> 6);
        if (n >= NN) return;
        const float* fr = feat + n * 32;
        float acc = 0.f;
#pragma unroll
        for (int c = 0; c < 32; c++) acc += fr[c] * WT[c * 64 + o];
        acc += bo;
        y[(size_t)n * 64 + o] = lrelu(acc);
    }
}

// =============================================================================
extern "C" void kernel_launch(void* const* d_in, const int* in_sizes, int n_in,
                              void* d_out, int out_size) {
    const float* x     = (const float*)d_in[0];
    const int*   ei    = (const int*)d_in[1];
    const float* eattr = (const float*)d_in[2];
    const float* W0    = (const float*)d_in[3];
    const float* b0    = (const float*)d_in[4];
    const float* bng   = (const float*)d_in[5];
    const float* bnb   = (const float*)d_in[6];
    const float* bnm   = (const float*)d_in[7];
    const float* bnv   = (const float*)d_in[8];
    const float* Wl[2]   = {(const float*)d_in[9],  (const float*)d_in[16]};
    const float* bl[2]   = {(const float*)d_in[10], (const float*)d_in[17]};
    const float* Wr[2]   = {(const float*)d_in[11], (const float*)d_in[18]};
    const float* br[2]   = {(const float*)d_in[12], (const float*)d_in[19]};
    const float* We[2]   = {(const float*)d_in[13], (const float*)d_in[20]};
    const float* att[2]  = {(const float*)d_in[14], (const float*)d_in[21]};
    const float* bias[2] = {(const float*)d_in[15], (const float*)d_in[22]};
    const float* Wout  = (const float*)d_in[23];
    const float* bout  = (const float*)d_in[24];
    float* y = (float*)d_out;

    float *f0, *f1, *f2, *den0, *den1;
    cudaGetSymbolAddress((void**)&f0, g_f0);
    cudaGetSymbolAddress((void**)&f1, g_f1);
    cudaGetSymbolAddress((void**)&f2, g_f2);
    cudaGetSymbolAddress((void**)&den0, g_den);
    den1 = den0 + NN * HH;

    k_embed_plus<<<(NN + 63) / 64, 256>>>(x, W0, b0, bng, bnb, bnm, bnv,
                                          bias[0], bias[1]);                         // 0
    k_loop_accum<<<(EE * 4 + 255) / 256, 256>>>(ei, eattr);                          // 1

    const float* fin[2]  = {f0, f1};
    float*       fden[2] = {den0, den1};
    float*       fout[2] = {f1, f2};
    for (int l = 0; l < 2; l++) {
        k_xlxr<<<(NN + 31) / 32, 256>>>(fin[l], Wl[l], bl[l], Wr[l], br[l]);         // 2, 6
        k_alpha<<<(ET + 63) / 64, 256>>>(ei, eattr, We[l], att[l], fden[l]);         // 3 <- profiled, 7
        k_rcp<<<(NN * HH + 255) / 256, 256>>>(fden[l]);                              // 4, 8
        k_aggregate<<<(ET + 63) / 64, 256>>>(ei, fden[l], fout[l]);                  // 5, 9
    }
    k_final<<<(NN + 63) / 64, 256>>>(f2, Wout, bout, y);                             // 10
}